// round 2
// baseline (speedup 1.0000x reference)
#include <cuda_runtime.h>
#include <cuda_bf16.h>
#include <cstdint>

#define N_NODES 16384
#define D       128
#define R_T     5
#define H_H     4
#define E_EDGES 262144

// ---------------- device scratch (static globals; no allocation) ----------------
__device__ float g_K[R_T * N_NODES * D];      // 41.9 MB
__device__ float g_Q[R_T * N_NODES * D];      // 41.9 MB
__device__ float g_V[R_T * N_NODES * D];      // 41.9 MB
__device__ float g_score[E_EDGES * 4];        // 4 MB   [E][H]
__device__ float g_agg[N_NODES * 512];        // 33.5MB [N][H*D]
__device__ int   g_deg[N_NODES];
__device__ int   g_cursor[N_NODES];
__device__ int   g_off[N_NODES + 1];
__device__ int   g_eids[E_EDGES];

// ---------------- utility ----------------
__device__ __forceinline__ void atomicMaxFloatShared(float* addr, float val) {
    int* ia = (int*)addr;
    int old = __float_as_int(*addr);
    while (__int_as_float(old) < val) {
        int assumed = old;
        old = atomicCAS(ia, assumed, __float_as_int(val));
        if (old == assumed) break;
    }
}

// ---------------- kernels ----------------
__global__ void zero_kernel() {
    int i = blockIdx.x * 256 + threadIdx.x;
    if (i < N_NODES) { g_deg[i] = 0; g_cursor[i] = 0; }
}

// QKV projections: gridDim = (N/64, R, 3). Block 256 threads computes a
// [64 nodes x 128 cols] tile. Thread: 8 nodes x 4 cols register micro-tile.
__global__ void __launch_bounds__(256) qkv_gemm(
    const float* __restrict__ h,
    const float* __restrict__ Wk, const float* __restrict__ bk,
    const float* __restrict__ Wq, const float* __restrict__ bq,
    const float* __restrict__ Wv, const float* __restrict__ bv)
{
    int r = blockIdx.y;
    int which = blockIdx.z;
    const float* W; const float* b; float* out;
    if (which == 0)      { W = Wk; b = bk; out = g_K; }
    else if (which == 1) { W = Wq; b = bq; out = g_Q; }
    else                 { W = Wv; b = bv; out = g_V; }
    W += r * D * D;
    b += r * D;
    out += (size_t)r * N_NODES * D;

    __shared__ float hs[64 * D];  // 32 KB
    int nodeBase = blockIdx.x * 64;
    {
        const float4* hsrc = (const float4*)(h + (size_t)nodeBase * D);
        float4* hdst = (float4*)hs;
        for (int i = threadIdx.x; i < 64 * D / 4; i += 256) hdst[i] = hsrc[i];
    }
    __syncthreads();

    int cg = threadIdx.x & 31;   // column group (4 cols)
    int ng = threadIdx.x >> 5;   // node group (8 nodes)
    int c0 = cg * 4;

    float acc[8][4];
    float4 bb = *(const float4*)(b + c0);
    #pragma unroll
    for (int t = 0; t < 8; t++) {
        acc[t][0] = bb.x; acc[t][1] = bb.y; acc[t][2] = bb.z; acc[t][3] = bb.w;
    }

    const float4* Wp = (const float4*)(W + c0);   // row i at Wp[i*32]
    #pragma unroll 4
    for (int i = 0; i < D; i++) {
        float4 w = Wp[i * 32];
        float hv[8];
        #pragma unroll
        for (int t = 0; t < 8; t++) hv[t] = hs[(ng * 8 + t) * D + i];
        #pragma unroll
        for (int t = 0; t < 8; t++) {
            acc[t][0] += hv[t] * w.x;
            acc[t][1] += hv[t] * w.y;
            acc[t][2] += hv[t] * w.z;
            acc[t][3] += hv[t] * w.w;
        }
    }

    #pragma unroll
    for (int t = 0; t < 8; t++) {
        float4 o = make_float4(acc[t][0], acc[t][1], acc[t][2], acc[t][3]);
        *((float4*)(out + (size_t)(nodeBase + ng * 8 + t) * D + c0)) = o;
    }
}

// Per-edge attention scores: warp per edge. score[e][h] = (k_h . q_h)/sqrt(32)
// Also accumulates the dst-degree histogram (lane 0), fused to save a pass.
__global__ void __launch_bounds__(256) score_kernel(
    const int* __restrict__ src, const int* __restrict__ dst,
    const int* __restrict__ etype)
{
    int e = blockIdx.x * 8 + (threadIdx.x >> 5);
    int lane = threadIdx.x & 31;
    int r = etype[e];
    int s = src[e];
    int dn = dst[e];
    if (lane == 0) atomicAdd(&g_deg[dn], 1);
    const float4* kp = (const float4*)(g_K + ((size_t)r * N_NODES + s)  * D);
    const float4* qp = (const float4*)(g_Q + ((size_t)r * N_NODES + dn) * D);
    float4 k4 = kp[lane];
    float4 q4 = qp[lane];
    float p = k4.x * q4.x + k4.y * q4.y + k4.z * q4.z + k4.w * q4.w;
    // reduce within 8-lane groups (one head each): lanes l..l^7
    p += __shfl_xor_sync(0xffffffff, p, 1);
    p += __shfl_xor_sync(0xffffffff, p, 2);
    p += __shfl_xor_sync(0xffffffff, p, 4);
    if ((lane & 7) == 0)
        g_score[e * 4 + (lane >> 3)] = p * 0.1767766952966369f;  // 1/sqrt(32)
}

// Single-block exclusive scan of g_deg (16384 = 512 x 32)
__global__ void __launch_bounds__(512) scan_kernel() {
    __shared__ int sums[512];
    int tid = threadIdx.x;
    int base = tid * 32;
    int local[32];
    int s = 0;
    #pragma unroll
    for (int i = 0; i < 32; i++) { local[i] = g_deg[base + i]; s += local[i]; }
    sums[tid] = s;
    __syncthreads();
    for (int st = 1; st < 512; st <<= 1) {
        int v = (tid >= st) ? sums[tid - st] : 0;
        __syncthreads();
        sums[tid] += v;
        __syncthreads();
    }
    int run = sums[tid] - s;  // exclusive prefix
    #pragma unroll
    for (int i = 0; i < 32; i++) { g_off[base + i] = run; run += local[i]; }
    if (tid == 511) g_off[N_NODES] = run;
}

__global__ void scatter_kernel(const int* __restrict__ dst) {
    int e = blockIdx.x * 256 + threadIdx.x;
    if (e < E_EDGES) {
        int dn = dst[e];
        int pos = g_off[dn] + atomicAdd(&g_cursor[dn], 1);
        g_eids[pos] = e;
    }
}

// Per-destination-node softmax + weighted aggregation. Block (128 thr) per node.
__global__ void __launch_bounds__(128) agg_kernel(
    const int* __restrict__ src, const int* __restrict__ etype)
{
    int n = blockIdx.x;
    int start = g_off[n];
    int deg = g_off[n + 1] - start;
    int tid = threadIdx.x;

    __shared__ float s_max[R_T * H_H];
    __shared__ float s_den[R_T * H_H];
    __shared__ float s_inv[R_T * H_H];
    __shared__ int    s_s[32];
    __shared__ int    s_r[32];
    __shared__ float4 s_a[32];

    if (tid < R_T * H_H) { s_max[tid] = -3.402823466e38f; s_den[tid] = 0.f; }
    __syncthreads();

    // pass 1: per-(rel,head) max
    for (int j = tid; j < deg; j += 128) {
        int e = g_eids[start + j];
        int r = etype[e];
        float4 sc = *(const float4*)(g_score + e * 4);
        atomicMaxFloatShared(&s_max[r * 4 + 0], sc.x);
        atomicMaxFloatShared(&s_max[r * 4 + 1], sc.y);
        atomicMaxFloatShared(&s_max[r * 4 + 2], sc.z);
        atomicMaxFloatShared(&s_max[r * 4 + 3], sc.w);
    }
    __syncthreads();

    // pass 2: per-(rel,head) denominator
    for (int j = tid; j < deg; j += 128) {
        int e = g_eids[start + j];
        int r = etype[e];
        float4 sc = *(const float4*)(g_score + e * 4);
        atomicAdd(&s_den[r * 4 + 0], __expf(sc.x - s_max[r * 4 + 0]));
        atomicAdd(&s_den[r * 4 + 1], __expf(sc.y - s_max[r * 4 + 1]));
        atomicAdd(&s_den[r * 4 + 2], __expf(sc.z - s_max[r * 4 + 2]));
        atomicAdd(&s_den[r * 4 + 3], __expf(sc.w - s_max[r * 4 + 3]));
    }
    __syncthreads();
    if (tid < R_T * H_H) s_inv[tid] = 1.0f / s_den[tid];
    __syncthreads();

    // pass 3: chunked weighted aggregation; thread owns output dim 'tid'
    float a0 = 0.f, a1 = 0.f, a2 = 0.f, a3 = 0.f;
    for (int j0 = 0; j0 < deg; j0 += 32) {
        int m = min(32, deg - j0);
        if (tid < m) {
            int e = g_eids[start + j0 + tid];
            int r = etype[e];
            float4 sc = *(const float4*)(g_score + e * 4);
            float4 a;
            a.x = __expf(sc.x - s_max[r * 4 + 0]) * s_inv[r * 4 + 0];
            a.y = __expf(sc.y - s_max[r * 4 + 1]) * s_inv[r * 4 + 1];
            a.z = __expf(sc.z - s_max[r * 4 + 2]) * s_inv[r * 4 + 2];
            a.w = __expf(sc.w - s_max[r * 4 + 3]) * s_inv[r * 4 + 3];
            s_a[tid] = a;
            s_s[tid] = src[e];
            s_r[tid] = r;
        }
        __syncthreads();
        for (int jj = 0; jj < m; jj++) {
            int sN = s_s[jj];
            int r  = s_r[jj];
            float4 a = s_a[jj];
            float v = g_V[((size_t)r * N_NODES + sN) * D + tid];
            a0 += a.x * v; a1 += a.y * v; a2 += a.z * v; a3 += a.w * v;
        }
        __syncthreads();
    }

    float* o = g_agg + (size_t)n * 512;
    o[tid]       = a0;
    o[128 + tid] = a1;
    o[256 + tid] = a2;
    o[384 + tid] = a3;
}

// Final projection: out[N,128] = g_agg[N,512] @ Wt[512,128] + bt
__global__ void __launch_bounds__(256) final_gemm(
    const float* __restrict__ Wt, const float* __restrict__ bt,
    float* __restrict__ out)
{
    __shared__ float hs[64 * D];  // 32 KB chunk of g_agg
    int nodeBase = blockIdx.x * 64;
    int cg = threadIdx.x & 31;
    int ng = threadIdx.x >> 5;
    int c0 = cg * 4;

    float acc[8][4];
    float4 bb = *(const float4*)(bt + c0);
    #pragma unroll
    for (int t = 0; t < 8; t++) {
        acc[t][0] = bb.x; acc[t][1] = bb.y; acc[t][2] = bb.z; acc[t][3] = bb.w;
    }

    const float4* agg4 = (const float4*)g_agg;  // row stride 128 float4
    for (int kb = 0; kb < 4; kb++) {
        for (int idx = threadIdx.x; idx < 64 * 32; idx += 256) {
            int row = idx >> 5;
            int c4  = idx & 31;
            ((float4*)hs)[idx] = agg4[(size_t)(nodeBase + row) * 128 + kb * 32 + c4];
        }
        __syncthreads();

        const float4* Wp = (const float4*)(Wt + c0);
        #pragma unroll 4
        for (int i = 0; i < D; i++) {
            float4 w = Wp[(kb * D + i) * 32];
            float hv[8];
            #pragma unroll
            for (int t = 0; t < 8; t++) hv[t] = hs[(ng * 8 + t) * D + i];
            #pragma unroll
            for (int t = 0; t < 8; t++) {
                acc[t][0] += hv[t] * w.x;
                acc[t][1] += hv[t] * w.y;
                acc[t][2] += hv[t] * w.z;
                acc[t][3] += hv[t] * w.w;
            }
        }
        __syncthreads();
    }

    #pragma unroll
    for (int t = 0; t < 8; t++) {
        float4 o = make_float4(acc[t][0], acc[t][1], acc[t][2], acc[t][3]);
        *((float4*)(out + (size_t)(nodeBase + ng * 8 + t) * D + c0)) = o;
    }
}

// ---------------- launch ----------------
extern "C" void kernel_launch(void* const* d_in, const int* in_sizes, int n_in,
                              void* d_out, int out_size)
{
    const float* h  = (const float*)d_in[0];
    const float* Wk = (const float*)d_in[1];
    const float* bk = (const float*)d_in[2];
    const float* Wq = (const float*)d_in[3];
    const float* bq = (const float*)d_in[4];
    const float* Wv = (const float*)d_in[5];
    const float* bv = (const float*)d_in[6];
    const float* Wt = (const float*)d_in[7];
    const float* bt = (const float*)d_in[8];
    const int* src   = (const int*)d_in[9];
    const int* dst   = (const int*)d_in[10];
    const int* etype = (const int*)d_in[11];
    float* out = (float*)d_out;

    zero_kernel<<<(N_NODES + 255) / 256, 256>>>();
    qkv_gemm<<<dim3(N_NODES / 64, R_T, 3), 256>>>(h, Wk, bk, Wq, bq, Wv, bv);
    score_kernel<<<E_EDGES / 8, 256>>>(src, dst, etype);
    scan_kernel<<<1, 512>>>();
    scatter_kernel<<<E_EDGES / 256, 256>>>(dst);
    agg_kernel<<<N_NODES, 128>>>(src, etype);
    final_gemm<<<N_NODES / 64, 256>>>(Wt, bt, out);
}

// round 4
// speedup vs baseline: 1.1899x; 1.1899x over previous
#include <cuda_runtime.h>
#include <cuda_bf16.h>
#include <cstdint>

#define N_NODES 16384
#define D       128
#define R_T     5
#define H_H     4
#define E_EDGES 262144

typedef unsigned long long u64;

// ---------------- device scratch (static globals; no allocation) ----------------
__device__ float g_K[R_T * N_NODES * D];      // 41.9 MB
__device__ float g_Q[R_T * N_NODES * D];      // 41.9 MB
__device__ float g_V[R_T * N_NODES * D];      // 41.9 MB
__device__ float g_score[E_EDGES * 4];        // 4 MB   [E][H]
__device__ float g_agg[N_NODES * 512];        // 33.5MB [N][H*D]
__device__ int   g_deg[N_NODES];
__device__ int   g_cursor[N_NODES];
__device__ int   g_off[N_NODES + 1];
__device__ int   g_eids[E_EDGES];

// ---------------- f32x2 packed-FMA helpers (Blackwell FFMA2 path) ----------------
__device__ __forceinline__ u64 pack2(float lo, float hi) {
    u64 r;
    asm("mov.b64 %0, {%1, %2};" : "=l"(r) : "f"(lo), "f"(hi));
    return r;
}
__device__ __forceinline__ void unpack2(u64 v, float& lo, float& hi) {
    asm("mov.b64 {%0, %1}, %2;" : "=f"(lo), "=f"(hi) : "l"(v));
}
__device__ __forceinline__ u64 fma2(u64 a, u64 b, u64 c) {
    u64 d;
    asm("fma.rn.f32x2 %0, %1, %2, %3;" : "=l"(d) : "l"(a), "l"(b), "l"(c));
    return d;
}

__device__ __forceinline__ void atomicMaxFloatShared(float* addr, float val) {
    int* ia = (int*)addr;
    int old = __float_as_int(*addr);
    while (__int_as_float(old) < val) {
        int assumed = old;
        old = atomicCAS(ia, assumed, __float_as_int(val));
        if (old == assumed) break;
    }
}

// ---------------- kernels ----------------
__global__ void zero_kernel() {
    int i = blockIdx.x * 256 + threadIdx.x;
    if (i < N_NODES) { g_deg[i] = 0; g_cursor[i] = 0; }
}

// Core f32x2 GEMM tile: [64 nodes x 128 cols] per block, thread = 8 nodes x 4 cols.
// hs_t is the K-major-transposed input tile: hs_t[k*64 + node].
// Accumulators pack node-pairs: acc[p][c] = {out[n2p][c0+c], out[n2p+1][c0+c]}.
__device__ __forceinline__ void gemm_tile_f32x2(
    const float* __restrict__ hs_t, const float* __restrict__ W,
    int c0, int ng, u64 acc[4][4])
{
    const float4* Wp = (const float4*)(W + c0);
    #pragma unroll 4
    for (int i = 0; i < D; i++) {
        float4 w = Wp[i * 32];
        u64 wd0 = pack2(w.x, w.x);
        u64 wd1 = pack2(w.y, w.y);
        u64 wd2 = pack2(w.z, w.z);
        u64 wd3 = pack2(w.w, w.w);
        const u64* hp = (const u64*)(hs_t + i * 64 + ng * 8);
        #pragma unroll
        for (int p = 0; p < 4; p++) {
            u64 hpv = hp[p];
            acc[p][0] = fma2(hpv, wd0, acc[p][0]);
            acc[p][1] = fma2(hpv, wd1, acc[p][1]);
            acc[p][2] = fma2(hpv, wd2, acc[p][2]);
            acc[p][3] = fma2(hpv, wd3, acc[p][3]);
        }
    }
}

// QKV projections: gridDim = (N/64, R, 3).
__global__ void __launch_bounds__(256) qkv_gemm(
    const float* __restrict__ h,
    const float* __restrict__ Wk, const float* __restrict__ bk,
    const float* __restrict__ Wq, const float* __restrict__ bq,
    const float* __restrict__ Wv, const float* __restrict__ bv)
{
    int r = blockIdx.y;
    int which = blockIdx.z;
    const float* W; const float* b; float* out;
    if (which == 0)      { W = Wk; b = bk; out = g_K; }
    else if (which == 1) { W = Wq; b = bq; out = g_Q; }
    else                 { W = Wv; b = bv; out = g_V; }
    W += r * D * D;
    b += r * D;
    out += (size_t)r * N_NODES * D;

    __shared__ float hs_t[D * 64];  // 32 KB, [k][node]
    int nodeBase = blockIdx.x * 64;

    // Transposed stage: lanes get consecutive nodes -> conflict-free STS.
    {
        const float4* h4 = (const float4*)h;  // row stride = 32 float4
        for (int idx = threadIdx.x; idx < 64 * 32; idx += 256) {
            int c4 = idx >> 6;       // which float4 column (0..31)
            int n  = idx & 63;       // node within tile
            float4 v = h4[(size_t)(nodeBase + n) * 32 + c4];
            hs_t[(c4 * 4 + 0) * 64 + n] = v.x;
            hs_t[(c4 * 4 + 1) * 64 + n] = v.y;
            hs_t[(c4 * 4 + 2) * 64 + n] = v.z;
            hs_t[(c4 * 4 + 3) * 64 + n] = v.w;
        }
    }
    __syncthreads();

    int cg = threadIdx.x & 31;   // column group (4 cols)
    int ng = threadIdx.x >> 5;   // node group (8 nodes)
    int c0 = cg * 4;

    u64 acc[4][4];
    float4 bb = *(const float4*)(b + c0);
    #pragma unroll
    for (int p = 0; p < 4; p++) {
        acc[p][0] = pack2(bb.x, bb.x);
        acc[p][1] = pack2(bb.y, bb.y);
        acc[p][2] = pack2(bb.z, bb.z);
        acc[p][3] = pack2(bb.w, bb.w);
    }

    gemm_tile_f32x2(hs_t, W, c0, ng, acc);

    #pragma unroll
    for (int p = 0; p < 4; p++) {
        float lo0, hi0, lo1, hi1, lo2, hi2, lo3, hi3;
        unpack2(acc[p][0], lo0, hi0);
        unpack2(acc[p][1], lo1, hi1);
        unpack2(acc[p][2], lo2, hi2);
        unpack2(acc[p][3], lo3, hi3);
        int n0 = nodeBase + ng * 8 + 2 * p;
        *((float4*)(out + (size_t)n0 * D + c0))       = make_float4(lo0, lo1, lo2, lo3);
        *((float4*)(out + (size_t)(n0 + 1) * D + c0)) = make_float4(hi0, hi1, hi2, hi3);
    }
}

// Per-edge attention scores: warp per edge + fused dst-degree histogram.
__global__ void __launch_bounds__(256) score_kernel(
    const int* __restrict__ src, const int* __restrict__ dst,
    const int* __restrict__ etype)
{
    int e = blockIdx.x * 8 + (threadIdx.x >> 5);
    int lane = threadIdx.x & 31;
    int r = etype[e];
    int s = src[e];
    int dn = dst[e];
    if (lane == 0) atomicAdd(&g_deg[dn], 1);
    const float4* kp = (const float4*)(g_K + ((size_t)r * N_NODES + s)  * D);
    const float4* qp = (const float4*)(g_Q + ((size_t)r * N_NODES + dn) * D);
    float4 k4 = kp[lane];
    float4 q4 = qp[lane];
    float p = k4.x * q4.x + k4.y * q4.y + k4.z * q4.z + k4.w * q4.w;
    p += __shfl_xor_sync(0xffffffff, p, 1);
    p += __shfl_xor_sync(0xffffffff, p, 2);
    p += __shfl_xor_sync(0xffffffff, p, 4);
    if ((lane & 7) == 0)
        g_score[e * 4 + (lane >> 3)] = p * 0.1767766952966369f;  // 1/sqrt(32)
}

// Single-block exclusive scan of g_deg (16384 = 512 x 32).
// Register-resident: each thread loads its contiguous 32-run via 8x int4
// (LDG.128, MLP=8, L2-resident data), shuffle-scans the 512 partials,
// writes back via 8x STG.128. No large smem.
__global__ void __launch_bounds__(512) scan_kernel() {
    __shared__ int wsum[16];
    int tid = threadIdx.x;
    int base = tid * 32;

    int4 v[8];
    const int4* dp = (const int4*)(g_deg + base);
    #pragma unroll
    for (int i = 0; i < 8; i++) v[i] = dp[i];

    int s = 0;
    #pragma unroll
    for (int i = 0; i < 8; i++) s += v[i].x + v[i].y + v[i].z + v[i].w;

    // Warp-shuffle inclusive scan of the 512 partials.
    int lane = tid & 31, warp = tid >> 5;
    int inc = s;
    #pragma unroll
    for (int st = 1; st < 32; st <<= 1) {
        int u = __shfl_up_sync(0xffffffff, inc, st);
        if (lane >= st) inc += u;
    }
    if (lane == 31) wsum[warp] = inc;
    __syncthreads();
    if (warp == 0 && lane < 16) {
        int w = wsum[lane];
        #pragma unroll
        for (int st = 1; st < 16; st <<= 1) {
            int u = __shfl_up_sync(0xffff, w, st);
            if (lane >= st) w += u;
        }
        wsum[lane] = w;
    }
    __syncthreads();
    int run = inc - s + (warp > 0 ? wsum[warp - 1] : 0);  // exclusive prefix

    // Convert the 32 local values to exclusive prefixes in registers.
    int4* op = (int4*)(g_off + base);
    #pragma unroll
    for (int i = 0; i < 8; i++) {
        int4 o;
        o.x = run;           run += v[i].x;
        o.y = run;           run += v[i].y;
        o.z = run;           run += v[i].z;
        o.w = run;           run += v[i].w;
        op[i] = o;
    }
    if (tid == 511) g_off[N_NODES] = run;
}

__global__ void scatter_kernel(const int* __restrict__ dst) {
    int e = blockIdx.x * 256 + threadIdx.x;
    if (e < E_EDGES) {
        int dn = dst[e];
        int pos = g_off[dn] + atomicAdd(&g_cursor[dn], 1);
        g_eids[pos] = e;
    }
}

// Per-destination-node softmax + weighted aggregation. Block (128 thr) per node.
__global__ void __launch_bounds__(128) agg_kernel(
    const int* __restrict__ src, const int* __restrict__ etype)
{
    int n = blockIdx.x;
    int start = g_off[n];
    int deg = g_off[n + 1] - start;
    int tid = threadIdx.x;

    __shared__ float s_max[R_T * H_H];
    __shared__ float s_den[R_T * H_H];
    __shared__ float s_inv[R_T * H_H];
    __shared__ int    s_s[32];
    __shared__ int    s_r[32];
    __shared__ float4 s_a[32];

    if (tid < R_T * H_H) { s_max[tid] = -3.402823466e38f; s_den[tid] = 0.f; }
    __syncthreads();

    for (int j = tid; j < deg; j += 128) {
        int e = g_eids[start + j];
        int r = etype[e];
        float4 sc = *(const float4*)(g_score + e * 4);
        atomicMaxFloatShared(&s_max[r * 4 + 0], sc.x);
        atomicMaxFloatShared(&s_max[r * 4 + 1], sc.y);
        atomicMaxFloatShared(&s_max[r * 4 + 2], sc.z);
        atomicMaxFloatShared(&s_max[r * 4 + 3], sc.w);
    }
    __syncthreads();

    for (int j = tid; j < deg; j += 128) {
        int e = g_eids[start + j];
        int r = etype[e];
        float4 sc = *(const float4*)(g_score + e * 4);
        atomicAdd(&s_den[r * 4 + 0], __expf(sc.x - s_max[r * 4 + 0]));
        atomicAdd(&s_den[r * 4 + 1], __expf(sc.y - s_max[r * 4 + 1]));
        atomicAdd(&s_den[r * 4 + 2], __expf(sc.z - s_max[r * 4 + 2]));
        atomicAdd(&s_den[r * 4 + 3], __expf(sc.w - s_max[r * 4 + 3]));
    }
    __syncthreads();
    if (tid < R_T * H_H) s_inv[tid] = 1.0f / s_den[tid];
    __syncthreads();

    float a0 = 0.f, a1 = 0.f, a2 = 0.f, a3 = 0.f;
    for (int j0 = 0; j0 < deg; j0 += 32) {
        int m = min(32, deg - j0);
        if (tid < m) {
            int e = g_eids[start + j0 + tid];
            int r = etype[e];
            float4 sc = *(const float4*)(g_score + e * 4);
            float4 a;
            a.x = __expf(sc.x - s_max[r * 4 + 0]) * s_inv[r * 4 + 0];
            a.y = __expf(sc.y - s_max[r * 4 + 1]) * s_inv[r * 4 + 1];
            a.z = __expf(sc.z - s_max[r * 4 + 2]) * s_inv[r * 4 + 2];
            a.w = __expf(sc.w - s_max[r * 4 + 3]) * s_inv[r * 4 + 3];
            s_a[tid] = a;
            s_s[tid] = src[e];
            s_r[tid] = r;
        }
        __syncthreads();
        for (int jj = 0; jj < m; jj++) {
            int sN = s_s[jj];
            int r  = s_r[jj];
            float4 a = s_a[jj];
            float v = g_V[((size_t)r * N_NODES + sN) * D + tid];
            a0 += a.x * v; a1 += a.y * v; a2 += a.z * v; a3 += a.w * v;
        }
        __syncthreads();
    }

    float* o = g_agg + (size_t)n * 512;
    o[tid]       = a0;
    o[128 + tid] = a1;
    o[256 + tid] = a2;
    o[384 + tid] = a3;
}

// Final projection: out[N,128] = g_agg[N,512] @ Wt[512,128] + bt (f32x2 path)
__global__ void __launch_bounds__(256) final_gemm(
    const float* __restrict__ Wt, const float* __restrict__ bt,
    float* __restrict__ out)
{
    __shared__ float hs_t[D * 64];  // 32 KB per-chunk transposed tile
    int nodeBase = blockIdx.x * 64;
    int cg = threadIdx.x & 31;
    int ng = threadIdx.x >> 5;
    int c0 = cg * 4;

    u64 acc[4][4];
    float4 bb = *(const float4*)(bt + c0);
    #pragma unroll
    for (int p = 0; p < 4; p++) {
        acc[p][0] = pack2(bb.x, bb.x);
        acc[p][1] = pack2(bb.y, bb.y);
        acc[p][2] = pack2(bb.z, bb.z);
        acc[p][3] = pack2(bb.w, bb.w);
    }

    const float4* agg4 = (const float4*)g_agg;  // row stride 128 float4
    for (int kb = 0; kb < 4; kb++) {
        for (int idx = threadIdx.x; idx < 64 * 32; idx += 256) {
            int c4 = idx >> 6;
            int n  = idx & 63;
            float4 v = agg4[(size_t)(nodeBase + n) * 128 + kb * 32 + c4];
            hs_t[(c4 * 4 + 0) * 64 + n] = v.x;
            hs_t[(c4 * 4 + 1) * 64 + n] = v.y;
            hs_t[(c4 * 4 + 2) * 64 + n] = v.z;
            hs_t[(c4 * 4 + 3) * 64 + n] = v.w;
        }
        __syncthreads();
        gemm_tile_f32x2(hs_t, Wt + (size_t)kb * D * D, c0, ng, acc);
        __syncthreads();
    }

    #pragma unroll
    for (int p = 0; p < 4; p++) {
        float lo0, hi0, lo1, hi1, lo2, hi2, lo3, hi3;
        unpack2(acc[p][0], lo0, hi0);
        unpack2(acc[p][1], lo1, hi1);
        unpack2(acc[p][2], lo2, hi2);
        unpack2(acc[p][3], lo3, hi3);
        int n0 = nodeBase + ng * 8 + 2 * p;
        *((float4*)(out + (size_t)n0 * D + c0))       = make_float4(lo0, lo1, lo2, lo3);
        *((float4*)(out + (size_t)(n0 + 1) * D + c0)) = make_float4(hi0, hi1, hi2, hi3);
    }
}

// ---------------- launch ----------------
extern "C" void kernel_launch(void* const* d_in, const int* in_sizes, int n_in,
                              void* d_out, int out_size)
{
    const float* h  = (const float*)d_in[0];
    const float* Wk = (const float*)d_in[1];
    const float* bk = (const float*)d_in[2];
    const float* Wq = (const float*)d_in[3];
    const float* bq = (const float*)d_in[4];
    const float* Wv = (const float*)d_in[5];
    const float* bv = (const float*)d_in[6];
    const float* Wt = (const float*)d_in[7];
    const float* bt = (const float*)d_in[8];
    const int* src   = (const int*)d_in[9];
    const int* dst   = (const int*)d_in[10];
    const int* etype = (const int*)d_in[11];
    float* out = (float*)d_out;

    zero_kernel<<<(N_NODES + 255) / 256, 256>>>();
    qkv_gemm<<<dim3(N_NODES / 64, R_T, 3), 256>>>(h, Wk, bk, Wq, bq, Wv, bv);
    score_kernel<<<E_EDGES / 8, 256>>>(src, dst, etype);
    scan_kernel<<<1, 512>>>();
    scatter_kernel<<<E_EDGES / 256, 256>>>(dst);
    agg_kernel<<<N_NODES, 128>>>(src, etype);
    final_gemm<<<N_NODES / 64, 256>>>(Wt, bt, out);
}